// round 1
// baseline (speedup 1.0000x reference)
#include <cuda_runtime.h>
#include <math.h>

#define NTOK 16384
#define DM   2048
#define NE   64
#define CAP  640
#define BT   128
#define KB   16
#define NCHUNK (DM / KB)   // 128

// ---------------- device scratch (no allocations allowed) ----------------
__device__ int   g_e12[NTOK];       // e1 | (e2<<8)
__device__ float g_w12[2 * NTOK];   // w1n, w2n per token
__device__ int   g_cnt1[NE];        // top-1 histogram (wave-0 counts)
__device__ float g_counts[NE];      // per-expert normalized dispatch mass
__device__ float g_zsum;            // sum of logits^2

// ---------------- init: re-zero scratch every graph replay ----------------
__global__ void init_kernel() {
    int t = threadIdx.x;
    if (t < NE) { g_cnt1[t] = 0; g_counts[t] = 0.0f; }
    if (t == 0) g_zsum = 0.0f;
}

// ---------------- stage A: GEMM + softmax + top2 + histogram + z ----------------
__global__ __launch_bounds__(256) void gemm_router_kernel(
    const float* __restrict__ x, const float* __restrict__ W,
    float* __restrict__ out_rw)
{
    __shared__ float xs[2][KB][132];   // transposed x tile: xs[k][token]
    __shared__ float ws[2][KB][68];    // transposed W tile: ws[k][expert]
    __shared__ float ls[64][65];       // logits half-tile for epilogue
    __shared__ float zred[8];

    const int tid = threadIdx.x;
    const int tg  = tid & 15;          // token group: 8 tokens each
    const int eg  = tid >> 4;          // expert group: 4 experts each
    const int bt0 = blockIdx.x * BT;

    float acc[8][4];
#pragma unroll
    for (int i = 0; i < 8; i++)
#pragma unroll
        for (int j = 0; j < 4; j++) acc[i][j] = 0.0f;

    // ---- load chunk 0 ----
#pragma unroll
    for (int i = 0; i < 2; i++) {
        int idx = i * 256 + tid;
        int t = idx >> 2, kq = idx & 3;
        float4 v = *reinterpret_cast<const float4*>(x + (size_t)(bt0 + t) * DM + kq * 4);
        xs[0][kq * 4 + 0][t] = v.x; xs[0][kq * 4 + 1][t] = v.y;
        xs[0][kq * 4 + 2][t] = v.z; xs[0][kq * 4 + 3][t] = v.w;
    }
    {
        int e = tid >> 2, kq = tid & 3;
        float4 v = *reinterpret_cast<const float4*>(W + (size_t)e * DM + kq * 4);
        ws[0][kq * 4 + 0][e] = v.x; ws[0][kq * 4 + 1][e] = v.y;
        ws[0][kq * 4 + 2][e] = v.z; ws[0][kq * 4 + 3][e] = v.w;
    }
    __syncthreads();

    // ---- main K loop, double buffered ----
    for (int kc = 0; kc < NCHUNK; kc++) {
        const int b = kc & 1;
        float4 px0, px1, pw;
        const bool more = (kc + 1 < NCHUNK);
        if (more) {
            const int k0 = (kc + 1) * KB;
            {
                int idx = tid;             // i = 0
                int t = idx >> 2, kq = idx & 3;
                px0 = *reinterpret_cast<const float4*>(x + (size_t)(bt0 + t) * DM + k0 + kq * 4);
            }
            {
                int idx = 256 + tid;       // i = 1
                int t = idx >> 2, kq = idx & 3;
                px1 = *reinterpret_cast<const float4*>(x + (size_t)(bt0 + t) * DM + k0 + kq * 4);
            }
            {
                int e = tid >> 2, kq = tid & 3;
                pw = *reinterpret_cast<const float4*>(W + (size_t)e * DM + k0 + kq * 4);
            }
        }

#pragma unroll
        for (int kk = 0; kk < KB; kk++) {
            float4 xa = *reinterpret_cast<const float4*>(&xs[b][kk][tg * 8]);
            float4 xb = *reinterpret_cast<const float4*>(&xs[b][kk][tg * 8 + 4]);
            float4 wv = *reinterpret_cast<const float4*>(&ws[b][kk][eg * 4]);
            float xv[8] = {xa.x, xa.y, xa.z, xa.w, xb.x, xb.y, xb.z, xb.w};
            float wr[4] = {wv.x, wv.y, wv.z, wv.w};
#pragma unroll
            for (int i = 0; i < 8; i++)
#pragma unroll
                for (int j = 0; j < 4; j++)
                    acc[i][j] = fmaf(xv[i], wr[j], acc[i][j]);
        }

        if (more) {
            const int nb = b ^ 1;
            {
                int idx = tid; int t = idx >> 2, kq = idx & 3;
                xs[nb][kq * 4 + 0][t] = px0.x; xs[nb][kq * 4 + 1][t] = px0.y;
                xs[nb][kq * 4 + 2][t] = px0.z; xs[nb][kq * 4 + 3][t] = px0.w;
            }
            {
                int idx = 256 + tid; int t = idx >> 2, kq = idx & 3;
                xs[nb][kq * 4 + 0][t] = px1.x; xs[nb][kq * 4 + 1][t] = px1.y;
                xs[nb][kq * 4 + 2][t] = px1.z; xs[nb][kq * 4 + 3][t] = px1.w;
            }
            {
                int e = tid >> 2, kq = tid & 3;
                ws[nb][kq * 4 + 0][e] = pw.x; ws[nb][kq * 4 + 1][e] = pw.y;
                ws[nb][kq * 4 + 2][e] = pw.z; ws[nb][kq * 4 + 3][e] = pw.w;
            }
        }
        __syncthreads();
    }

    // ---- epilogue: softmax + top2 per row, two 64-row halves ----
    const int warp = tid >> 5, lane = tid & 31;
    float zacc = 0.0f;

    for (int h = 0; h < 2; h++) {
        __syncthreads();
        if ((tg >> 3) == h) {
            const int trow = (tg & 7) * 8;
#pragma unroll
            for (int i = 0; i < 8; i++)
#pragma unroll
                for (int j = 0; j < 4; j++)
                    ls[trow + i][eg * 4 + j] = acc[i][j];
        }
        __syncthreads();

        for (int j = 0; j < 8; j++) {
            const int r = warp * 8 + j;
            const int token = bt0 + h * 64 + r;
            float a  = ls[r][lane];
            float bv = ls[r][lane + 32];
            zacc += a * a + bv * bv;

            float mx = fmaxf(a, bv);
#pragma unroll
            for (int off = 16; off; off >>= 1)
                mx = fmaxf(mx, __shfl_xor_sync(0xffffffffu, mx, off));

            float pa = expf(a - mx), pb = expf(bv - mx);
            float s = pa + pb;
#pragma unroll
            for (int off = 16; off; off >>= 1)
                s += __shfl_xor_sync(0xffffffffu, s, off);

            out_rw[(size_t)token * NE + lane]      = pa / s;
            out_rw[(size_t)token * NE + lane + 32] = pb / s;

            // per-lane sorted top-2 on unnormalized exp (same order as weights)
            float v1, v2; int i1, i2;
            if (pa >= pb) { v1 = pa; i1 = lane;      v2 = pb; i2 = lane + 32; }
            else          { v1 = pb; i1 = lane + 32; v2 = pa; i2 = lane; }

#pragma unroll
            for (int off = 16; off; off >>= 1) {
                float o1 = __shfl_xor_sync(0xffffffffu, v1, off);
                int  oi1 = __shfl_xor_sync(0xffffffffu, i1, off);
                float o2 = __shfl_xor_sync(0xffffffffu, v2, off);
                int  oi2 = __shfl_xor_sync(0xffffffffu, i2, off);
                bool awins = (v1 > o1) || (v1 == o1 && i1 < oi1);
                if (awins) {
                    bool keep = (v2 > o1) || (v2 == o1 && i2 < oi1);
                    if (!keep) { v2 = o1; i2 = oi1; }
                } else {
                    bool btwo = (o2 > v1) || (o2 == v1 && oi2 < i1);
                    float nv2; int ni2;
                    if (btwo) { nv2 = o2; ni2 = oi2; }
                    else      { nv2 = v1; ni2 = i1; }
                    v1 = o1; i1 = oi1; v2 = nv2; i2 = ni2;
                }
            }

            if (lane == 0) {
                float w1 = v1 / s, w2 = v2 / s;
                float sw = w1 + w2;
                float w1n = w1 / (sw + 1e-8f);
                float w2n = w2 / (sw + 1e-8f);
                g_e12[token] = i1 | (i2 << 8);
                g_w12[2 * token]     = w1n;
                g_w12[2 * token + 1] = w2n;
                atomicAdd(&g_cnt1[i1], 1);
            }
        }
    }

    // ---- z-loss partial reduce ----
#pragma unroll
    for (int off = 16; off; off >>= 1)
        zacc += __shfl_xor_sync(0xffffffffu, zacc, off);
    if (lane == 0) zred[warp] = zacc;
    __syncthreads();
    if (warp == 0) {
        float t = (lane < 8) ? zred[lane] : 0.0f;
#pragma unroll
        for (int off = 4; off; off >>= 1)
            t += __shfl_xor_sync(0xffffffffu, t, off);
        if (lane == 0) atomicAdd(&g_zsum, t);
    }
}

// ---------------- stage B: dispatch mask write + normalized counts ----------------
__global__ __launch_bounds__(256) void dispatch_kernel(float* __restrict__ out_nd)
{
    const int gt = blockIdx.x * 256 + threadIdx.x;
    const int token = gt >> 4;       // 16 threads per token
    const int c4 = gt & 15;
    if (token >= NTOK) return;

    const int e12 = g_e12[token];
    const int e1 = e12 & 0xff, e2 = (e12 >> 8) & 0xff;
    const float w1n = g_w12[2 * token];
    const float w2n = g_w12[2 * token + 1];
    const bool acc2 = (g_cnt1[e2] < CAP);
    const float rs = w1n + (acc2 ? w2n : 0.0f);
    const float den = rs + 1e-8f;
    const float d1 = w1n / den;
    const float d2 = acc2 ? (w2n / den) : 0.0f;

    float4 v = make_float4(0.f, 0.f, 0.f, 0.f);
    const int c0 = c4 * 4;
    int r1 = e1 - c0;
    if (r1 == 0) v.x = d1; else if (r1 == 1) v.y = d1;
    else if (r1 == 2) v.z = d1; else if (r1 == 3) v.w = d1;
    int r2 = e2 - c0;
    if (r2 == 0) v.x = d2; else if (r2 == 1) v.y = d2;
    else if (r2 == 2) v.z = d2; else if (r2 == 3) v.w = d2;

    *reinterpret_cast<float4*>(out_nd + (size_t)token * NE + c0) = v;

    if (c4 == 0) {
        atomicAdd(&g_counts[e1], d1);
        if (acc2) atomicAdd(&g_counts[e2], d2);
    }
}

// ---------------- stage C: scalar loss ----------------
__global__ void loss_kernel(float* __restrict__ out)
{
    const int lane = threadIdx.x;   // 32 threads
    const float invN = 1.0f / (float)NTOK;
    const float tgt = 512.0f / (float)NTOK;
    float d0 = g_counts[lane] * invN - tgt;
    float d1 = g_counts[lane + 32] * invN - tgt;
    float s = d0 * d0 + d1 * d1;
#pragma unroll
    for (int off = 16; off; off >>= 1)
        s += __shfl_xor_sync(0xffffffffu, s, off);
    if (lane == 0) {
        float lb = s / 64.0f;
        float z = g_zsum / (float)((size_t)NTOK * NE);
        out[(size_t)2 * NTOK * NE] = 1e-3f * z + 1e-3f * lb;
    }
}

// ---------------- launch ----------------
extern "C" void kernel_launch(void* const* d_in, const int* in_sizes, int n_in,
                              void* d_out, int out_size)
{
    const float* x = (const float*)d_in[0];
    const float* W = (const float*)d_in[1];
    if (n_in >= 2 && in_sizes[0] == NE * DM) {  // defensive: swap if order reversed
        x = (const float*)d_in[1];
        W = (const float*)d_in[0];
    }
    float* out = (float*)d_out;

    init_kernel<<<1, 64>>>();
    gemm_router_kernel<<<NTOK / BT, 256>>>(x, W, out);
    dispatch_kernel<<<(NTOK * 16) / 256, 256>>>(out + (size_t)NTOK * NE);
    loss_kernel<<<1, 32>>>(out);
}